// round 11
// baseline (speedup 1.0000x reference)
#include <cuda_runtime.h>
#include <cuda_fp16.h>
#include <math.h>
#include <cstdint>

// ---------------- Problem constants ----------------
#define B_  64
#define S_  256
#define H_  768
#define L_  12
#define NH_ 12
#define HD_ 64
#define FF_ 3072
#define NTOK (B_ * S_)          // 16384
#define NL_ 2
#define QS_ 2304                // fused qkv row stride

// ---------------- Scratch (static device globals; no allocation) ----------------
__device__ float g_h  [NTOK * H_];
__device__ float g_tmp[NTOK * H_];
__device__ float g_qkv[(size_t)NTOK * QS_];

__device__ __half g_hh[NTOK * H_];
__device__ __half g_hl[NTOK * H_];
__device__ __half g_ch[NTOK * H_];
__device__ __half g_cl[NTOK * H_];
__device__ __half g_fh[(size_t)NTOK * FF_];
__device__ __half g_fl[(size_t)NTOK * FF_];

// transposed weights: [L][N][K] (K-major rows), single fp16
__device__ __half g_Wqkv[(size_t)L_ * QS_ * H_];
__device__ __half g_Wo  [(size_t)L_ * H_ * H_];
__device__ __half g_W1  [(size_t)L_ * H_ * FF_];
__device__ __half g_W2  [(size_t)L_ * FF_ * H_];
__device__ float  g_bqkv[L_ * QS_];

// ---------------- low-level helpers ----------------
__device__ __forceinline__ uint32_t smem_u32(const void* p) {
    uint32_t a;
    asm("{ .reg .u64 t; cvta.to.shared.u64 t, %1; cvt.u32.u64 %0, t; }" : "=r"(a) : "l"(p));
    return a;
}
__device__ __forceinline__ void cp16(uint32_t dst, const void* src) {
    asm volatile("cp.async.cg.shared.global [%0], [%1], 16;" :: "r"(dst), "l"(src) : "memory");
}
__device__ __forceinline__ void cp_commit() { asm volatile("cp.async.commit_group;" ::: "memory"); }
__device__ __forceinline__ void cp_wait0()  { asm volatile("cp.async.wait_group 0;" ::: "memory"); }
__device__ __forceinline__ void cp_wait1()  { asm volatile("cp.async.wait_group 1;" ::: "memory"); }

__device__ __forceinline__ void ldm_x4(uint32_t* r, uint32_t addr) {
    asm volatile("ldmatrix.sync.aligned.m8n8.x4.shared.b16 {%0,%1,%2,%3}, [%4];"
                 : "=r"(r[0]), "=r"(r[1]), "=r"(r[2]), "=r"(r[3]) : "r"(addr));
}
__device__ __forceinline__ void mma16816(float* d, const uint32_t* a, const uint32_t* b) {
    asm volatile("mma.sync.aligned.m16n8k16.row.col.f32.f16.f16.f32 "
                 "{%0,%1,%2,%3}, {%4,%5,%6,%7}, {%8,%9}, {%0,%1,%2,%3};"
                 : "+f"(d[0]), "+f"(d[1]), "+f"(d[2]), "+f"(d[3])
                 : "r"(a[0]), "r"(a[1]), "r"(a[2]), "r"(a[3]), "r"(b[0]), "r"(b[1]));
}

__device__ __forceinline__ void split2h(float v, __half& h, __half& l) {
    h = __float2half_rn(v);
    l = __float2half_rn(v - __half2float(h));
}
__device__ __forceinline__ uint32_t pack_h2(__half a, __half b) {
    return (uint32_t)__half_as_ushort(a) | ((uint32_t)__half_as_ushort(b) << 16);
}

// ---------------- Block reduction helper ----------------
__device__ __forceinline__ float block_sum(float v, float* red) {
    #pragma unroll
    for (int o = 16; o; o >>= 1) v += __shfl_xor_sync(0xffffffffu, v, o);
    int w = threadIdx.x >> 5, l = threadIdx.x & 31;
    if (l == 0) red[w] = v;
    __syncthreads();
    if (w == 0) {
        v = (l < (int)(blockDim.x >> 5)) ? red[l] : 0.0f;
        #pragma unroll
        for (int o = 16; o; o >>= 1) v += __shfl_xor_sync(0xffffffffu, v, o);
        if (l == 0) red[0] = v;
    }
    __syncthreads();
    float r = red[0];
    __syncthreads();
    return r;
}

// ---------------- Weight prep ----------------
__global__ void prep_w4_kernel(const float* __restrict__ WQ,
                               const float* __restrict__ WK,
                               const float* __restrict__ WV,
                               const float* __restrict__ WO,
                               __half* __restrict__ wqkv,
                               __half* __restrict__ wo) {
    __shared__ float t[32][33];
    int zz = blockIdx.z;
    int l = zz >> 2, w = zz & 3;
    int k0 = blockIdx.y * 32, n0 = blockIdx.x * 32;
    const float* Wp = ((w == 0) ? WQ : (w == 1) ? WK : (w == 2) ? WV : WO)
                      + (size_t)l * H_ * H_;
    for (int r = threadIdx.y; r < 32; r += 8)
        t[r][threadIdx.x] = Wp[(size_t)(k0 + r) * H_ + n0 + threadIdx.x];
    __syncthreads();
    for (int r = threadIdx.y; r < 32; r += 8) {
        int n = n0 + r, k = k0 + threadIdx.x;
        __half hv = __float2half_rn(t[threadIdx.x][r]);
        if (w < 3)
            wqkv[(size_t)l * QS_ * H_ + (size_t)(w * H_ + n) * H_ + k] = hv;
        else
            wo[(size_t)l * H_ * H_ + (size_t)n * H_ + k] = hv;
    }
}

__global__ void prep_w_kernel(const float* __restrict__ W,
                              __half* __restrict__ Wd,
                              int K, int N) {
    __shared__ float t[32][33];
    int l  = blockIdx.z;
    int k0 = blockIdx.y * 32, n0 = blockIdx.x * 32;
    const float* Wp = W + (size_t)l * K * N;
    for (int r = threadIdx.y; r < 32; r += 8)
        t[r][threadIdx.x] = Wp[(size_t)(k0 + r) * N + n0 + threadIdx.x];
    __syncthreads();
    for (int r = threadIdx.y; r < 32; r += 8) {
        int n = n0 + r, k = k0 + threadIdx.x;
        Wd[(size_t)l * N * K + (size_t)n * K + k] = __float2half_rn(t[threadIdx.x][r]);
    }
}

__global__ void concat_bias_kernel(const float* __restrict__ bq,
                                   const float* __restrict__ bk,
                                   const float* __restrict__ bv,
                                   float* __restrict__ dst) {
    int i = blockIdx.x * 256 + threadIdx.x;
    if (i >= L_ * QS_) return;
    int l = i / QS_, n = i % QS_;
    float v = (n < H_) ? bq[l * H_ + n]
            : (n < 2 * H_) ? bk[l * H_ + n - H_]
            : bv[l * H_ + n - 2 * H_];
    dst[i] = v;
}

// ---------------- Embedding + LayerNorm (+ fp16 hi/lo split) ----------------
__global__ void embed_ln_kernel(const int* __restrict__ ids,
                                const int* __restrict__ tt,
                                const float* __restrict__ we,
                                const float* __restrict__ pe,
                                const float* __restrict__ te,
                                const float* __restrict__ s,
                                const float* __restrict__ b,
                                float* __restrict__ out,
                                __half* __restrict__ oh,
                                __half* __restrict__ ol) {
    __shared__ float red[32];
    int tok = blockIdx.x;
    int tid = threadIdx.x;
    int srow = tok % S_;
    int id = ids[tok];
    int t  = tt[tok];
    float x[3];
    #pragma unroll
    for (int r = 0; r < 3; r++) {
        int i = tid + 256 * r;
        x[r] = we[(size_t)id * H_ + i] + pe[(size_t)srow * H_ + i] + te[(size_t)t * H_ + i];
    }
    float sum = block_sum(x[0] + x[1] + x[2], red);
    float m = sum * (1.0f / H_);
    float vs = 0.0f;
    #pragma unroll
    for (int r = 0; r < 3; r++) { float d = x[r] - m; vs += d * d; }
    vs = block_sum(vs, red);
    float inv = rsqrtf(vs * (1.0f / H_) + 1e-12f);
    #pragma unroll
    for (int r = 0; r < 3; r++) {
        int i = tid + 256 * r;
        float vv = (x[r] - m) * inv * s[i] + b[i];
        size_t o = (size_t)tok * H_ + i;
        out[o] = vv;
        __half hh, ll; split2h(vv, hh, ll);
        oh[o] = hh; ol[o] = ll;
    }
}

// ---------------- Residual add + LayerNorm (in place) + fp16 hi/lo ----------------
__global__ void add_ln_kernel(float* __restrict__ h,
                              const float* __restrict__ t,
                              const float* __restrict__ s,
                              const float* __restrict__ b,
                              __half* __restrict__ oh,
                              __half* __restrict__ ol) {
    __shared__ float red[32];
    int tok = blockIdx.x;
    int tid = threadIdx.x;
    float x[3];
    #pragma unroll
    for (int r = 0; r < 3; r++) {
        int i = tid + 256 * r;
        x[r] = h[(size_t)tok * H_ + i] + t[(size_t)tok * H_ + i];
    }
    float sum = block_sum(x[0] + x[1] + x[2], red);
    float m = sum * (1.0f / H_);
    float vs = 0.0f;
    #pragma unroll
    for (int r = 0; r < 3; r++) { float d = x[r] - m; vs += d * d; }
    vs = block_sum(vs, red);
    float inv = rsqrtf(vs * (1.0f / H_) + 1e-12f);
    #pragma unroll
    for (int r = 0; r < 3; r++) {
        int i = tid + 256 * r;
        float vv = (x[r] - m) * inv * s[i] + b[i];
        size_t o = (size_t)tok * H_ + i;
        h[o] = vv;
        __half hh, ll; split2h(vv, hh, ll);
        oh[o] = hh; ol[o] = ll;
    }
}

// ---------------- mma.sync GEMM, fp16x2 emulation ----------------
// CTA tile 128(M) x 64(N), warp tile 32x32, BK=32, 3-stage cp.async, 3 CTAs/SM.
// Rows 64B (32 halves), 16B-chunk XOR swizzle: chunk ^= (row>>1)&3 (R8-proven).
// Inner-loop MMA order = R9's proven interleaved schedule.
#define ROWB 64
#define ARRB 8192            // A array: 128 rows * 64B
#define WOFF (2 * ARRB)      // W array: 64 rows * 64B = 4096
#define STGB 20480           // 8K + 8K + 4K
#define GSMEM (3 * STGB)     // 61440 ; x3 CTAs = 180KB < 228KB

__device__ __forceinline__ uint32_t swz_off(uint32_t row, uint32_t ch) {
    return row * ROWB + ((ch ^ ((row >> 1) & 3)) << 4);
}

__device__ __forceinline__ void load_stage(
    uint32_t s0, int tid, int bm, int bn, int kc, int K,
    const __half* __restrict__ Ah, const __half* __restrict__ Al,
    const __half* __restrict__ W) {
    #pragma unroll
    for (int i = 0; i < 5; i++) {
        int t = tid + i * 256;                 // 0..1279
        int ch = t & 3;
        uint32_t dst;
        const __half* src;
        if (t < 512) {                         // A hi, rows 0..127
            int row = t >> 2;
            src = Ah + (size_t)(bm + row) * K + kc + ch * 8;
            dst = s0 + swz_off(row, ch);
        } else if (t < 1024) {                 // A lo
            int row = (t - 512) >> 2;
            src = Al + (size_t)(bm + row) * K + kc + ch * 8;
            dst = s0 + ARRB + swz_off(row, ch);
        } else {                               // W, rows 0..63
            int row = (t - 1024) >> 2;
            src = W + (size_t)(bn + row) * K + kc + ch * 8;
            dst = s0 + WOFF + swz_off(row, ch);
        }
        cp16(dst, src);
    }
    cp_commit();
}

__device__ __forceinline__ void compute_stage(uint32_t s0, int wm, int wn, int lane,
                                              float (&acc)[2][4][4]) {
    uint32_t ldrow = lane & 15;
    uint32_t ldch  = lane >> 4;          // 16B chunk parity within k-slice
    #pragma unroll
    for (int kk = 0; kk < 2; kk++) {
        uint32_t ch = kk * 2 + ldch;     // 0..3
        uint32_t ah[2][4], al[2][4];
        #pragma unroll
        for (int mi = 0; mi < 2; mi++) {
            uint32_t r = wm * 32 + mi * 16 + ldrow;
            uint32_t off = swz_off(r, ch);
            ldm_x4(ah[mi], s0 + off);
            ldm_x4(al[mi], s0 + ARRB + off);
        }
        #pragma unroll
        for (int g = 0; g < 2; g++) {
            uint32_t r = wn * 32 + g * 16 + ldrow;
            uint32_t w4[4];
            ldm_x4(w4, s0 + WOFF + swz_off(r, ch));
            uint32_t b0[2] = {w4[0], w4[2]}, b1[2] = {w4[1], w4[3]};
            #pragma unroll
            for (int mi = 0; mi < 2; mi++) {
                mma16816(acc[mi][2 * g],     ah[mi], b0);
                mma16816(acc[mi][2 * g + 1], ah[mi], b1);
                mma16816(acc[mi][2 * g],     al[mi], b0);
                mma16816(acc[mi][2 * g + 1], al[mi], b1);
            }
        }
    }
}

__global__ void __launch_bounds__(256, 3) gemm_mma(
    const __half* __restrict__ Ah, const __half* __restrict__ Al,
    const __half* __restrict__ W,
    const float* __restrict__ bias,
    float* __restrict__ Cf,
    __half* __restrict__ Chi, __half* __restrict__ Clo,
    int M, int N, int K, int act) {
    extern __shared__ char smem[];
    uint32_t sb = smem_u32(smem);
    int tid = threadIdx.x, lane = tid & 31, wid = tid >> 5;
    int wm = wid & 3, wn = wid >> 2;
    int bm = blockIdx.y * 128, bn = blockIdx.x * 64;

    float acc[2][4][4];
    #pragma unroll
    for (int a = 0; a < 2; a++)
        #pragma unroll
        for (int b = 0; b < 4; b++)
            #pragma unroll
            for (int c = 0; c < 4; c++) acc[a][b][c] = 0.0f;

    const int NC = K / 32;   // 24 for K=768, 96 for K=3072
    load_stage(sb + 0 * STGB, tid, bm, bn, 0,  K, Ah, Al, W);
    load_stage(sb + 1 * STGB, tid, bm, bn, 32, K, Ah, Al, W);

    for (int c = 0; c < NC; c++) {
        if (c + 1 < NC) cp_wait1(); else cp_wait0();
        __syncthreads();
        if (c + 2 < NC)
            load_stage(sb + ((c + 2) % 3) * STGB, tid, bm, bn, (c + 2) * 32, K,
                       Ah, Al, W);
        compute_stage(sb + (c % 3) * STGB, wm, wn, lane, acc);
    }

    int tr = lane >> 2, tc = (lane & 3) * 2;
    #pragma unroll
    for (int mi = 0; mi < 2; mi++) {
        #pragma unroll
        for (int hr = 0; hr < 2; hr++) {
            int m = bm + wm * 32 + mi * 16 + hr * 8 + tr;
            #pragma unroll
            for (int ni = 0; ni < 4; ni++) {
                int n = bn + wn * 32 + ni * 8 + tc;
                float v0 = acc[mi][ni][hr * 2]     + bias[n];
                float v1 = acc[mi][ni][hr * 2 + 1] + bias[n + 1];
                if (act) {
                    v0 = 0.5f * v0 * (1.0f + erff(v0 * 0.70710678118654752f));
                    v1 = 0.5f * v1 * (1.0f + erff(v1 * 0.70710678118654752f));
                }
                if (Cf)
                    *(float2*)(Cf + (size_t)m * N + n) = make_float2(v0, v1);
                if (Chi) {
                    __half h0, l0, h1, l1;
                    split2h(v0, h0, l0);
                    split2h(v1, h1, l1);
                    *(uint32_t*)(Chi + (size_t)m * N + n) = pack_h2(h0, h1);
                    *(uint32_t*)(Clo + (size_t)m * N + n) = pack_h2(l0, l1);
                }
            }
        }
    }
}

// ---------------- MMA flash attention: one CTA per (b, head) ----------------
#define AKP 144              // K/Q pitch bytes (row = 64 halves + 8 pad)
#define AKH 72
#define AVP 528              // Vt pitch bytes (256*2 + 16)
#define SM_K  0
#define SM_QH (256 * AKP)
#define SM_QL (2 * 256 * AKP)
#define SM_VT (3 * 256 * AKP)
#define SM_BI (SM_VT + 64 * AVP)
#define ASMEM (SM_BI + 1024)

__global__ void __launch_bounds__(256, 1) attn_mma(
    const float* __restrict__ qkv,
    const int* __restrict__ mask,
    __half* __restrict__ Oh,
    __half* __restrict__ Ol) {
    extern __shared__ char smem[];
    uint32_t sb = smem_u32(smem);
    __half* Ksm  = (__half*)(smem + SM_K);
    __half* Qhsm = (__half*)(smem + SM_QH);
    __half* Qlsm = (__half*)(smem + SM_QL);
    __half* Vtsm = (__half*)(smem + SM_VT);
    float*  bsm  = (float*)(smem + SM_BI);

    int bh = blockIdx.x;
    int b = bh / NH_, h = bh % NH_;
    int tid = threadIdx.x, lane = tid & 31, w = tid >> 5;
    const size_t qbase = ((size_t)b * S_) * QS_ + (size_t)h * HD_;

    for (int idx = tid; idx < 256 * 16; idx += 256) {
        int j = idx >> 4, c4 = idx & 15;
        int d = c4 * 4;
        const float* row = qkv + qbase + (size_t)j * QS_;
        float4 qv = *(const float4*)(row + d);
        float4 kv = *(const float4*)(row + H_ + d);
        float4 vv = *(const float4*)(row + 2 * H_ + d);
        float qa[4] = {qv.x, qv.y, qv.z, qv.w};
        float ka[4] = {kv.x, kv.y, kv.z, kv.w};
        float va[4] = {vv.x, vv.y, vv.z, vv.w};
        #pragma unroll
        for (int i = 0; i < 4; i++) {
            __half hh, ll;
            split2h(qa[i], hh, ll);
            Qhsm[j * AKH + d + i] = hh;
            Qlsm[j * AKH + d + i] = ll;
            Ksm [j * AKH + d + i] = __float2half_rn(ka[i]);
            Vtsm[(d + i) * 264 + j] = __float2half_rn(va[i]);
        }
    }
    bsm[tid] = (1.0f - (float)mask[b * S_ + tid]) * -10000.0f;
    __syncthreads();

    const float scale = 0.125f;
    int tr = lane >> 2, tqc = (lane & 3) * 2;
    uint32_t ldrow = lane & 15;
    uint32_t ldoff = (lane >> 4) * 16;

    float acc_o[2][8][4];
    #pragma unroll
    for (int a = 0; a < 2; a++)
        #pragma unroll
        for (int n = 0; n < 8; n++)
            #pragma unroll
            for (int c = 0; c < 4; c++) acc_o[a][n][c] = 0.0f;
    float m_run[4] = {-1e30f, -1e30f, -1e30f, -1e30f};
    float l_run[4] = {0.0f, 0.0f, 0.0f, 0.0f};

    for (int chunk = 0; chunk < 4; chunk++) {
        float acc_s[2][8][4];
        #pragma unroll
        for (int a = 0; a < 2; a++)
            #pragma unroll
            for (int n = 0; n < 8; n++)
                #pragma unroll
                for (int c = 0; c < 4; c++) acc_s[a][n][c] = 0.0f;

        #pragma unroll
        for (int kk = 0; kk < 4; kk++) {
            uint32_t kb = kk * 32 + ldoff;
            uint32_t aqh[2][4], aql[2][4];
            #pragma unroll
            for (int mi = 0; mi < 2; mi++) {
                uint32_t r = w * 32 + mi * 16 + ldrow;
                ldm_x4(aqh[mi], sb + SM_QH + r * AKP + kb);
                ldm_x4(aql[mi], sb + SM_QL + r * AKP + kb);
            }
            #pragma unroll
            for (int g = 0; g < 4; g++) {
                uint32_t kr = chunk * 64 + g * 16 + ldrow;
                uint32_t w4[4];
                ldm_x4(w4, sb + SM_K + kr * AKP + kb);
                uint32_t b0[2] = {w4[0], w4[2]}, b1[2] = {w4[1], w4[3]};
                #pragma unroll
                for (int mi = 0; mi < 2; mi++) {
                    mma16816(acc_s[mi][2 * g],     aqh[mi], b0);
                    mma16816(acc_s[mi][2 * g + 1], aqh[mi], b1);
                    mma16816(acc_s[mi][2 * g],     aql[mi], b0);
                    mma16816(acc_s[mi][2 * g + 1], aql[mi], b1);
                }
            }
        }

        #pragma unroll
        for (int mi = 0; mi < 2; mi++)
            #pragma unroll
            for (int ni = 0; ni < 8; ni++) {
                int j0 = chunk * 64 + ni * 8 + tqc;
                float b0v = bsm[j0], b1v = bsm[j0 + 1];
                acc_s[mi][ni][0] = acc_s[mi][ni][0] * scale + b0v;
                acc_s[mi][ni][1] = acc_s[mi][ni][1] * scale + b1v;
                acc_s[mi][ni][2] = acc_s[mi][ni][2] * scale + b0v;
                acc_s[mi][ni][3] = acc_s[mi][ni][3] * scale + b1v;
            }

        #pragma unroll
        for (int mi = 0; mi < 2; mi++) {
            #pragma unroll
            for (int hf = 0; hf < 2; hf++) {
                int c0 = hf * 2, c1 = hf * 2 + 1;
                float mx = -1e30f;
                #pragma unroll
                for (int ni = 0; ni < 8; ni++)
                    mx = fmaxf(mx, fmaxf(acc_s[mi][ni][c0], acc_s[mi][ni][c1]));
                mx = fmaxf(mx, __shfl_xor_sync(0xffffffffu, mx, 1));
                mx = fmaxf(mx, __shfl_xor_sync(0xffffffffu, mx, 2));
                int si = mi * 2 + hf;
                float mn = fmaxf(m_run[si], mx);
                float corr = __expf(m_run[si] - mn);
                m_run[si] = mn;
                float rs = 0.0f;
                #pragma unroll
                for (int ni = 0; ni < 8; ni++) {
                    float p0 = __expf(acc_s[mi][ni][c0] - mn);
                    float p1 = __expf(acc_s[mi][ni][c1] - mn);
                    acc_s[mi][ni][c0] = p0;
                    acc_s[mi][ni][c1] = p1;
                    rs += p0 + p1;
                }
                rs += __shfl_xor_sync(0xffffffffu, rs, 1);
                rs += __shfl_xor_sync(0xffffffffu, rs, 2);
                l_run[si] = l_run[si] * corr + rs;
                #pragma unroll
                for (int ni = 0; ni < 8; ni++) {
                    acc_o[mi][ni][c0] *= corr;
                    acc_o[mi][ni][c1] *= corr;
                }
            }
        }

        #pragma unroll
        for (int t = 0; t < 4; t++) {
            uint32_t aph[2][4], apl[2][4];
            #pragma unroll
            for (int mi = 0; mi < 2; mi++) {
                float* S0 = acc_s[mi][2 * t];
                float* S1 = acc_s[mi][2 * t + 1];
                __half h0, l0, h1, l1;
                split2h(S0[0], h0, l0); split2h(S0[1], h1, l1);
                aph[mi][0] = pack_h2(h0, h1); apl[mi][0] = pack_h2(l0, l1);
                split2h(S0[2], h0, l0); split2h(S0[3], h1, l1);
                aph[mi][1] = pack_h2(h0, h1); apl[mi][1] = pack_h2(l0, l1);
                split2h(S1[0], h0, l0); split2h(S1[1], h1, l1);
                aph[mi][2] = pack_h2(h0, h1); apl[mi][2] = pack_h2(l0, l1);
                split2h(S1[2], h0, l0); split2h(S1[3], h1, l1);
                aph[mi][3] = pack_h2(h0, h1); apl[mi][3] = pack_h2(l0, l1);
            }
            #pragma unroll
            for (int g = 0; g < 4; g++) {
                uint32_t vr = g * 16 + ldrow;
                uint32_t w4[4];
                ldm_x4(w4, sb + SM_VT + vr * AVP + chunk * 128 + t * 32 + ldoff);
                uint32_t b0[2] = {w4[0], w4[2]}, b1[2] = {w4[1], w4[3]};
                #pragma unroll
                for (int mi = 0; mi < 2; mi++) {
                    mma16816(acc_o[mi][2 * g],     aph[mi], b0);
                    mma16816(acc_o[mi][2 * g + 1], aph[mi], b1);
                    mma16816(acc_o[mi][2 * g],     apl[mi], b0);
                    mma16816(acc_o[mi][2 * g + 1], apl[mi], b1);
                }
            }
        }
    }

    const size_t obase = ((size_t)b * S_) * H_ + (size_t)h * HD_;
    #pragma unroll
    for (int mi = 0; mi < 2; mi++) {
        float inv0 = 1.0f / l_run[mi * 2];
        float inv1 = 1.0f / l_run[mi * 2 + 1];
        int r0 = w * 32 + mi * 16 + tr;
        int r1 = r0 + 8;
        #pragma unroll
        for (int ni = 0; ni < 8; ni++) {
            int d = ni * 8 + tqc;
            float v0 = acc_o[mi][ni][0] * inv0, v1 = acc_o[mi][ni][1] * inv0;
            float v2 = acc_o[mi][ni][2] * inv1, v3 = acc_o[mi][ni][3] * inv1;
            __half h0, l0, h1, l1;
            split2h(v0, h0, l0); split2h(v1, h1, l1);
            *(uint32_t*)(Oh + obase + (size_t)r0 * H_ + d) = pack_h2(h0, h1);
            *(uint32_t*)(Ol + obase + (size_t)r0 * H_ + d) = pack_h2(l0, l1);
            split2h(v2, h0, l0); split2h(v3, h1, l1);
            *(uint32_t*)(Oh + obase + (size_t)r1 * H_ + d) = pack_h2(h0, h1);
            *(uint32_t*)(Ol + obase + (size_t)r1 * H_ + d) = pack_h2(l0, l1);
        }
    }
}

// ---------------- Classification head ----------------
__global__ void head_kernel(const float* __restrict__ h,
                            const int* __restrict__ ann,
                            const float* __restrict__ hw,
                            const float* __restrict__ hb,
                            float* __restrict__ out) {
    __shared__ float red[32];
    int b = blockIdx.x;
    int tid = threadIdx.x;
    int a = ann[b];
    const float* cls = h + (size_t)b * S_ * H_;
    const float* w = hw + (size_t)a * H_ * NL_;
    float a0 = 0.0f, a1 = 0.0f;
    for (int i = tid; i < H_; i += 256) {
        float c = cls[i];
        a0 = fmaf(c, w[i * NL_ + 0], a0);
        a1 = fmaf(c, w[i * NL_ + 1], a1);
    }
    a0 = block_sum(a0, red);
    a1 = block_sum(a1, red);
    if (tid == 0) {
        out[b * NL_ + 0] = a0 + hb[a * NL_ + 0];
        out[b * NL_ + 1] = a1 + hb[a * NL_ + 1];
    }
}

// ---------------- Host launcher ----------------
extern "C" void kernel_launch(void* const* d_in, const int* in_sizes, int n_in,
                              void* d_out, int out_size) {
    (void)in_sizes; (void)n_in; (void)out_size;
    const int*   ids   = (const int*)  d_in[0];
    const int*   amask = (const int*)  d_in[1];
    const int*   tt    = (const int*)  d_in[2];
    const int*   ann   = (const int*)  d_in[3];
    const float* we    = (const float*)d_in[4];
    const float* pe    = (const float*)d_in[5];
    const float* te    = (const float*)d_in[6];
    const float* elns  = (const float*)d_in[7];
    const float* elnb  = (const float*)d_in[8];
    const float* Wq    = (const float*)d_in[9];
    const float* bq    = (const float*)d_in[10];
    const float* Wk    = (const float*)d_in[11];
    const float* bk    = (const float*)d_in[12];
    const float* Wv    = (const float*)d_in[13];
    const float* bv    = (const float*)d_in[14];
    const float* Wo    = (const float*)d_in[15];
    const float* bo    = (const float*)d_in[16];
    const float* l1s   = (const float*)d_in[17];
    const float* l1b   = (const float*)d_in[18];
    const float* W1    = (const float*)d_in[19];
    const float* b1    = (const float*)d_in[20];
    const float* W2    = (const float*)d_in[21];
    const float* b2    = (const float*)d_in[22];
    const float* l2s   = (const float*)d_in[23];
    const float* l2b   = (const float*)d_in[24];
    const float* hw    = (const float*)d_in[25];
    const float* hb    = (const float*)d_in[26];
    float* out = (float*)d_out;

    float *h, *tmp, *qkv, *bqkv;
    __half *hh, *hl, *ch, *cl, *fh, *fl;
    __half *wqkv, *wo, *w1, *w2;
    cudaGetSymbolAddress((void**)&h,    g_h);
    cudaGetSymbolAddress((void**)&tmp,  g_tmp);
    cudaGetSymbolAddress((void**)&qkv,  g_qkv);
    cudaGetSymbolAddress((void**)&bqkv, g_bqkv);
    cudaGetSymbolAddress((void**)&hh,   g_hh);
    cudaGetSymbolAddress((void**)&hl,   g_hl);
    cudaGetSymbolAddress((void**)&ch,   g_ch);
    cudaGetSymbolAddress((void**)&cl,   g_cl);
    cudaGetSymbolAddress((void**)&fh,   g_fh);
    cudaGetSymbolAddress((void**)&fl,   g_fl);
    cudaGetSymbolAddress((void**)&wqkv, g_Wqkv);
    cudaGetSymbolAddress((void**)&wo,   g_Wo);
    cudaGetSymbolAddress((void**)&w1,   g_W1);
    cudaGetSymbolAddress((void**)&w2,   g_W2);

    cudaFuncSetAttribute(attn_mma,
                         cudaFuncAttributeMaxDynamicSharedMemorySize, ASMEM);
    cudaFuncSetAttribute(gemm_mma,
                         cudaFuncAttributeMaxDynamicSharedMemorySize, GSMEM);

    dim3 pb(32, 8);
    // Keep QKV gemm at my-launch #4 (process launch #6 under ncu -s 5).
    concat_bias_kernel<<<(L_ * QS_ + 255) / 256, 256>>>(bq, bk, bv, bqkv);
    prep_w4_kernel<<<dim3(H_ / 32, H_ / 32, L_ * 4), pb>>>(Wq, Wk, Wv, Wo, wqkv, wo);
    embed_ln_kernel<<<NTOK, 256>>>(ids, tt, we, pe, te, elns, elnb, h, hh, hl);

    dim3 gQKV(QS_ / 64, NTOK / 128);  // (36, 128)
    dim3 gH  (H_  / 64, NTOK / 128);  // (12, 128)
    dim3 gFF (FF_ / 64, NTOK / 128);  // (48, 128)

    for (int l = 0; l < L_; l++) {
        size_t wqo = (size_t)l * QS_ * H_;
        size_t woo = (size_t)l * H_ * H_;
        size_t wfo = (size_t)l * H_ * FF_;

        gemm_mma<<<gQKV, 256, GSMEM>>>(hh, hl, wqkv + wqo,
                                       bqkv + (size_t)l * QS_,
                                       qkv, nullptr, nullptr, NTOK, QS_, H_, 0);

        if (l == 0) {
            prep_w_kernel<<<dim3(FF_ / 32, H_ / 32, L_), pb>>>(W1, w1, H_, FF_);
            prep_w_kernel<<<dim3(H_ / 32, FF_ / 32, L_), pb>>>(W2, w2, FF_, H_);
        }

        attn_mma<<<B_ * NH_, 256, ASMEM>>>(qkv, amask, ch, cl);

        gemm_mma<<<gH, 256, GSMEM>>>(ch, cl, wo + woo,
                                     bo + (size_t)l * H_,
                                     tmp, nullptr, nullptr, NTOK, H_, H_, 0);
        add_ln_kernel<<<NTOK, 256>>>(h, tmp, l1s + (size_t)l * H_, l1b + (size_t)l * H_, hh, hl);

        gemm_mma<<<gFF, 256, GSMEM>>>(hh, hl, w1 + wfo,
                                      b1 + (size_t)l * FF_,
                                      nullptr, fh, fl, NTOK, FF_, H_, 1);
        gemm_mma<<<gH, 256, GSMEM>>>(fh, fl, w2 + wfo,
                                     b2 + (size_t)l * H_,
                                     tmp, nullptr, nullptr, NTOK, H_, FF_, 0);
        add_ln_kernel<<<NTOK, 256>>>(h, tmp, l2s + (size_t)l * H_, l2b + (size_t)l * H_, hh, hl);
    }

    head_kernel<<<B_, 256>>>(h, ann, hw, hb, out);
}

// round 12
// speedup vs baseline: 1.7542x; 1.7542x over previous
#include <cuda_runtime.h>
#include <cuda_fp16.h>
#include <math.h>
#include <cstdint>

// ---------------- Problem constants ----------------
#define B_  64
#define S_  256
#define H_  768
#define L_  12
#define NH_ 12
#define HD_ 64
#define FF_ 3072
#define NTOK (B_ * S_)          // 16384
#define NL_ 2
#define QS_ 2304                // fused qkv row stride

// ---------------- Scratch (static device globals; no allocation) ----------------
__device__ float g_h  [NTOK * H_];
__device__ float g_tmp[NTOK * H_];
__device__ float g_qkv[(size_t)NTOK * QS_];

__device__ __half g_hh[NTOK * H_];
__device__ __half g_ch[NTOK * H_];
__device__ __half g_fh[(size_t)NTOK * FF_];

// transposed weights: [L][N][K] (K-major rows), single fp16
__device__ __half g_Wqkv[(size_t)L_ * QS_ * H_];
__device__ __half g_Wo  [(size_t)L_ * H_ * H_];
__device__ __half g_W1  [(size_t)L_ * H_ * FF_];
__device__ __half g_W2  [(size_t)L_ * FF_ * H_];
__device__ float  g_bqkv[L_ * QS_];

// ---------------- low-level helpers ----------------
__device__ __forceinline__ uint32_t smem_u32(const void* p) {
    uint32_t a;
    asm("{ .reg .u64 t; cvta.to.shared.u64 t, %1; cvt.u32.u64 %0, t; }" : "=r"(a) : "l"(p));
    return a;
}
__device__ __forceinline__ void cp16(uint32_t dst, const void* src) {
    asm volatile("cp.async.cg.shared.global [%0], [%1], 16;" :: "r"(dst), "l"(src) : "memory");
}
__device__ __forceinline__ void cp_commit() { asm volatile("cp.async.commit_group;" ::: "memory"); }
__device__ __forceinline__ void cp_wait0()  { asm volatile("cp.async.wait_group 0;" ::: "memory"); }

__device__ __forceinline__ void ldm_x4(uint32_t* r, uint32_t addr) {
    asm volatile("ldmatrix.sync.aligned.m8n8.x4.shared.b16 {%0,%1,%2,%3}, [%4];"
                 : "=r"(r[0]), "=r"(r[1]), "=r"(r[2]), "=r"(r[3]) : "r"(addr));
}
__device__ __forceinline__ void mma16816(float* d, const uint32_t* a, const uint32_t* b) {
    asm volatile("mma.sync.aligned.m16n8k16.row.col.f32.f16.f16.f32 "
                 "{%0,%1,%2,%3}, {%4,%5,%6,%7}, {%8,%9}, {%0,%1,%2,%3};"
                 : "+f"(d[0]), "+f"(d[1]), "+f"(d[2]), "+f"(d[3])
                 : "r"(a[0]), "r"(a[1]), "r"(a[2]), "r"(a[3]), "r"(b[0]), "r"(b[1]));
}

__device__ __forceinline__ void split2h(float v, __half& h, __half& l) {
    h = __float2half_rn(v);
    l = __float2half_rn(v - __half2float(h));
}
__device__ __forceinline__ uint32_t pack_h2(__half a, __half b) {
    return (uint32_t)__half_as_ushort(a) | ((uint32_t)__half_as_ushort(b) << 16);
}

// ---------------- Block reduction helper ----------------
__device__ __forceinline__ float block_sum(float v, float* red) {
    #pragma unroll
    for (int o = 16; o; o >>= 1) v += __shfl_xor_sync(0xffffffffu, v, o);
    int w = threadIdx.x >> 5, l = threadIdx.x & 31;
    if (l == 0) red[w] = v;
    __syncthreads();
    if (w == 0) {
        v = (l < (int)(blockDim.x >> 5)) ? red[l] : 0.0f;
        #pragma unroll
        for (int o = 16; o; o >>= 1) v += __shfl_xor_sync(0xffffffffu, v, o);
        if (l == 0) red[0] = v;
    }
    __syncthreads();
    float r = red[0];
    __syncthreads();
    return r;
}

// ---------------- Weight prep ----------------
__global__ void prep_w4_kernel(const float* __restrict__ WQ,
                               const float* __restrict__ WK,
                               const float* __restrict__ WV,
                               const float* __restrict__ WO,
                               __half* __restrict__ wqkv,
                               __half* __restrict__ wo) {
    __shared__ float t[32][33];
    int zz = blockIdx.z;
    int l = zz >> 2, w = zz & 3;
    int k0 = blockIdx.y * 32, n0 = blockIdx.x * 32;
    const float* Wp = ((w == 0) ? WQ : (w == 1) ? WK : (w == 2) ? WV : WO)
                      + (size_t)l * H_ * H_;
    for (int r = threadIdx.y; r < 32; r += 8)
        t[r][threadIdx.x] = Wp[(size_t)(k0 + r) * H_ + n0 + threadIdx.x];
    __syncthreads();
    for (int r = threadIdx.y; r < 32; r += 8) {
        int n = n0 + r, k = k0 + threadIdx.x;
        __half hv = __float2half_rn(t[threadIdx.x][r]);
        if (w < 3)
            wqkv[(size_t)l * QS_ * H_ + (size_t)(w * H_ + n) * H_ + k] = hv;
        else
            wo[(size_t)l * H_ * H_ + (size_t)n * H_ + k] = hv;
    }
}

__global__ void prep_w_kernel(const float* __restrict__ W,
                              __half* __restrict__ Wd,
                              int K, int N) {
    __shared__ float t[32][33];
    int l  = blockIdx.z;
    int k0 = blockIdx.y * 32, n0 = blockIdx.x * 32;
    const float* Wp = W + (size_t)l * K * N;
    for (int r = threadIdx.y; r < 32; r += 8)
        t[r][threadIdx.x] = Wp[(size_t)(k0 + r) * N + n0 + threadIdx.x];
    __syncthreads();
    for (int r = threadIdx.y; r < 32; r += 8) {
        int n = n0 + r, k = k0 + threadIdx.x;
        Wd[(size_t)l * N * K + (size_t)n * K + k] = __float2half_rn(t[threadIdx.x][r]);
    }
}

__global__ void concat_bias_kernel(const float* __restrict__ bq,
                                   const float* __restrict__ bk,
                                   const float* __restrict__ bv,
                                   float* __restrict__ dst) {
    int i = blockIdx.x * 256 + threadIdx.x;
    if (i >= L_ * QS_) return;
    int l = i / QS_, n = i % QS_;
    float v = (n < H_) ? bq[l * H_ + n]
            : (n < 2 * H_) ? bk[l * H_ + n - H_]
            : bv[l * H_ + n - 2 * H_];
    dst[i] = v;
}

// ---------------- Embedding + LayerNorm ----------------
__global__ void embed_ln_kernel(const int* __restrict__ ids,
                                const int* __restrict__ tt,
                                const float* __restrict__ we,
                                const float* __restrict__ pe,
                                const float* __restrict__ te,
                                const float* __restrict__ s,
                                const float* __restrict__ b,
                                float* __restrict__ out,
                                __half* __restrict__ oh) {
    __shared__ float red[32];
    int tok = blockIdx.x;
    int tid = threadIdx.x;
    int srow = tok % S_;
    int id = ids[tok];
    int t  = tt[tok];
    float x[3];
    #pragma unroll
    for (int r = 0; r < 3; r++) {
        int i = tid + 256 * r;
        x[r] = we[(size_t)id * H_ + i] + pe[(size_t)srow * H_ + i] + te[(size_t)t * H_ + i];
    }
    float sum = block_sum(x[0] + x[1] + x[2], red);
    float m = sum * (1.0f / H_);
    float vs = 0.0f;
    #pragma unroll
    for (int r = 0; r < 3; r++) { float d = x[r] - m; vs += d * d; }
    vs = block_sum(vs, red);
    float inv = rsqrtf(vs * (1.0f / H_) + 1e-12f);
    #pragma unroll
    for (int r = 0; r < 3; r++) {
        int i = tid + 256 * r;
        float vv = (x[r] - m) * inv * s[i] + b[i];
        size_t o = (size_t)tok * H_ + i;
        out[o] = vv;
        oh[o] = __float2half_rn(vv);
    }
}

// ---------------- Residual add + LayerNorm (in place) ----------------
__global__ void add_ln_kernel(float* __restrict__ h,
                              const float* __restrict__ t,
                              const float* __restrict__ s,
                              const float* __restrict__ b,
                              __half* __restrict__ oh) {
    __shared__ float red[32];
    int tok = blockIdx.x;
    int tid = threadIdx.x;
    float x[3];
    #pragma unroll
    for (int r = 0; r < 3; r++) {
        int i = tid + 256 * r;
        x[r] = h[(size_t)tok * H_ + i] + t[(size_t)tok * H_ + i];
    }
    float sum = block_sum(x[0] + x[1] + x[2], red);
    float m = sum * (1.0f / H_);
    float vs = 0.0f;
    #pragma unroll
    for (int r = 0; r < 3; r++) { float d = x[r] - m; vs += d * d; }
    vs = block_sum(vs, red);
    float inv = rsqrtf(vs * (1.0f / H_) + 1e-12f);
    #pragma unroll
    for (int r = 0; r < 3; r++) {
        int i = tid + 256 * r;
        float vv = (x[r] - m) * inv * s[i] + b[i];
        size_t o = (size_t)tok * H_ + i;
        h[o] = vv;
        oh[o] = __float2half_rn(vv);
    }
}

// ---------------- mma.sync GEMM, fp16 x fp16, BK=64 double-buffer ----------------
// C[M,N] = A[M,K] @ W[N,K]^T + bias ; CTA tile 128x128, warp tile 32x64.
// Rows are 128B (64 halves), SW128-style XOR swizzle: chunk ^= row&7.
// R9-proven structure with the activation-lo array removed.
#define ROWB 128
#define ARRB 16384           // 128 rows * 128B
#define STGB 32768           // 2 arrays (A, W)
#define GSMEM (2 * STGB)     // 65536 ; x2 CTAs = 128KB < 228KB

__device__ __forceinline__ uint32_t swz_off(uint32_t row, uint32_t ch) {
    return row * ROWB + ((ch ^ (row & 7)) << 4);
}

__device__ __forceinline__ void load_stage(
    uint32_t s0, int tid, int bm, int bn, int kc, int K,
    const __half* __restrict__ A, const __half* __restrict__ W) {
    #pragma unroll
    for (int i = 0; i < 8; i++) {
        int t = tid + i * 256;                 // 0..2047
        int arr = t >> 10, c = t & 1023, row = c >> 3, ch = c & 7;
        const __half* base = (arr == 0) ? A : W;
        int grow = ((arr == 0) ? bm : bn) + row;
        cp16(s0 + arr * ARRB + swz_off(row, ch),
             base + (size_t)grow * K + kc + ch * 8);
    }
    cp_commit();
}

__device__ __forceinline__ void compute_stage(uint32_t s0, int wm, int wn, int lane,
                                              float (&acc)[2][8][4]) {
    uint32_t ldrow = lane & 15;
    uint32_t ldch  = lane >> 4;          // 16B chunk parity within k-slice
    #pragma unroll
    for (int kk = 0; kk < 4; kk++) {
        uint32_t ch = kk * 2 + ldch;     // 0..7
        uint32_t ah[2][4];
        #pragma unroll
        for (int mi = 0; mi < 2; mi++) {
            uint32_t r = wm * 32 + mi * 16 + ldrow;
            ldm_x4(ah[mi], s0 + swz_off(r, ch));
        }
        #pragma unroll
        for (int g = 0; g < 4; g++) {
            uint32_t r = wn * 64 + g * 16 + ldrow;
            uint32_t w4[4];
            ldm_x4(w4, s0 + ARRB + swz_off(r, ch));
            uint32_t b0[2] = {w4[0], w4[2]}, b1[2] = {w4[1], w4[3]};
            #pragma unroll
            for (int mi = 0; mi < 2; mi++) {
                mma16816(acc[mi][2 * g],     ah[mi], b0);
                mma16816(acc[mi][2 * g + 1], ah[mi], b1);
            }
        }
    }
}

__global__ void __launch_bounds__(256, 2) gemm_mma(
    const __half* __restrict__ A,
    const __half* __restrict__ W,
    const float* __restrict__ bias,
    float* __restrict__ Cf,
    __half* __restrict__ Ch,
    int M, int N, int K, int act) {
    extern __shared__ char smem[];
    uint32_t sb = smem_u32(smem);
    int tid = threadIdx.x, lane = tid & 31, wid = tid >> 5;
    int wm = wid & 3, wn = wid >> 2;
    int bm = blockIdx.y * 128, bn = blockIdx.x * 128;

    float acc[2][8][4];
    #pragma unroll
    for (int a = 0; a < 2; a++)
        #pragma unroll
        for (int b = 0; b < 8; b++)
            #pragma unroll
            for (int c = 0; c < 4; c++) acc[a][b][c] = 0.0f;

    const int NC = K / 64;   // 12 for K=768, 48 for K=3072
    load_stage(sb, tid, bm, bn, 0, K, A, W);

    for (int c = 0; c < NC; c++) {
        cp_wait0();
        __syncthreads();
        if (c + 1 < NC)
            load_stage(sb + ((c + 1) & 1) * STGB, tid, bm, bn, (c + 1) * 64, K, A, W);
        compute_stage(sb + (c & 1) * STGB, wm, wn, lane, acc);
    }

    int tr = lane >> 2, tc = (lane & 3) * 2;
    #pragma unroll
    for (int mi = 0; mi < 2; mi++) {
        #pragma unroll
        for (int hr = 0; hr < 2; hr++) {
            int m = bm + wm * 32 + mi * 16 + hr * 8 + tr;
            #pragma unroll
            for (int ni = 0; ni < 8; ni++) {
                int n = bn + wn * 64 + ni * 8 + tc;
                float v0 = acc[mi][ni][hr * 2]     + bias[n];
                float v1 = acc[mi][ni][hr * 2 + 1] + bias[n + 1];
                if (act) {
                    v0 = 0.5f * v0 * (1.0f + erff(v0 * 0.70710678118654752f));
                    v1 = 0.5f * v1 * (1.0f + erff(v1 * 0.70710678118654752f));
                }
                if (Cf)
                    *(float2*)(Cf + (size_t)m * N + n) = make_float2(v0, v1);
                if (Ch)
                    *(uint32_t*)(Ch + (size_t)m * N + n) =
                        pack_h2(__float2half_rn(v0), __float2half_rn(v1));
            }
        }
    }
}

// ---------------- MMA flash attention: one CTA per (b, head) ----------------
// Q hi/lo fp16 x K single; P hi/lo fp16 x V single (internal precision kept).
#define AKP 144              // K/Q pitch bytes (row = 64 halves + 8 pad)
#define AKH 72
#define AVP 528              // Vt pitch bytes (256*2 + 16)
#define SM_K  0
#define SM_QH (256 * AKP)
#define SM_QL (2 * 256 * AKP)
#define SM_VT (3 * 256 * AKP)
#define SM_BI (SM_VT + 64 * AVP)
#define ASMEM (SM_BI + 1024)

__global__ void __launch_bounds__(256, 1) attn_mma(
    const float* __restrict__ qkv,
    const int* __restrict__ mask,
    __half* __restrict__ Oh) {
    extern __shared__ char smem[];
    uint32_t sb = smem_u32(smem);
    __half* Ksm  = (__half*)(smem + SM_K);
    __half* Qhsm = (__half*)(smem + SM_QH);
    __half* Qlsm = (__half*)(smem + SM_QL);
    __half* Vtsm = (__half*)(smem + SM_VT);
    float*  bsm  = (float*)(smem + SM_BI);

    int bh = blockIdx.x;
    int b = bh / NH_, h = bh % NH_;
    int tid = threadIdx.x, lane = tid & 31, w = tid >> 5;
    const size_t qbase = ((size_t)b * S_) * QS_ + (size_t)h * HD_;

    for (int idx = tid; idx < 256 * 16; idx += 256) {
        int j = idx >> 4, c4 = idx & 15;
        int d = c4 * 4;
        const float* row = qkv + qbase + (size_t)j * QS_;
        float4 qv = *(const float4*)(row + d);
        float4 kv = *(const float4*)(row + H_ + d);
        float4 vv = *(const float4*)(row + 2 * H_ + d);
        float qa[4] = {qv.x, qv.y, qv.z, qv.w};
        float ka[4] = {kv.x, kv.y, kv.z, kv.w};
        float va[4] = {vv.x, vv.y, vv.z, vv.w};
        #pragma unroll
        for (int i = 0; i < 4; i++) {
            __half hh, ll;
            split2h(qa[i], hh, ll);
            Qhsm[j * AKH + d + i] = hh;
            Qlsm[j * AKH + d + i] = ll;
            Ksm [j * AKH + d + i] = __float2half_rn(ka[i]);
            Vtsm[(d + i) * 264 + j] = __float2half_rn(va[i]);
        }
    }
    bsm[tid] = (1.0f - (float)mask[b * S_ + tid]) * -10000.0f;
    __syncthreads();

    const float scale = 0.125f;
    int tr = lane >> 2, tqc = (lane & 3) * 2;
    uint32_t ldrow = lane & 15;
    uint32_t ldoff = (lane >> 4) * 16;

    float acc_o[2][8][4];
    #pragma unroll
    for (int a = 0; a < 2; a++)
        #pragma unroll
        for (int n = 0; n < 8; n++)
            #pragma unroll
            for (int c = 0; c < 4; c++) acc_o[a][n][c] = 0.0f;
    float m_run[4] = {-1e30f, -1e30f, -1e30f, -1e30f};
    float l_run[4] = {0.0f, 0.0f, 0.0f, 0.0f};

    for (int chunk = 0; chunk < 4; chunk++) {
        float acc_s[2][8][4];
        #pragma unroll
        for (int a = 0; a < 2; a++)
            #pragma unroll
            for (int n = 0; n < 8; n++)
                #pragma unroll
                for (int c = 0; c < 4; c++) acc_s[a][n][c] = 0.0f;

        #pragma unroll
        for (int kk = 0; kk < 4; kk++) {
            uint32_t kb = kk * 32 + ldoff;
            uint32_t aqh[2][4], aql[2][4];
            #pragma unroll
            for (int mi = 0; mi < 2; mi++) {
                uint32_t r = w * 32 + mi * 16 + ldrow;
                ldm_x4(aqh[mi], sb + SM_QH + r * AKP + kb);
                ldm_x4(aql[mi], sb + SM_QL + r * AKP + kb);
            }
            #pragma unroll
            for (int g = 0; g < 4; g++) {
                uint32_t kr = chunk * 64 + g * 16 + ldrow;
                uint32_t w4[4];
                ldm_x4(w4, sb + SM_K + kr * AKP + kb);
                uint32_t b0[2] = {w4[0], w4[2]}, b1[2] = {w4[1], w4[3]};
                #pragma unroll
                for (int mi = 0; mi < 2; mi++) {
                    mma16816(acc_s[mi][2 * g],     aqh[mi], b0);
                    mma16816(acc_s[mi][2 * g + 1], aqh[mi], b1);
                    mma16816(acc_s[mi][2 * g],     aql[mi], b0);
                    mma16816(acc_s[mi][2 * g + 1], aql[mi], b1);
                }
            }
        }

        #pragma unroll
        for (int mi = 0; mi < 2; mi++)
            #pragma unroll
            for (int ni = 0; ni < 8; ni++) {
                int j0 = chunk * 64 + ni * 8 + tqc;
                float b0v = bsm[j0], b1v = bsm[j0 + 1];
                acc_s[mi][ni][0] = acc_s[mi][ni][0] * scale + b0v;
                acc_s[mi][ni][1] = acc_s[mi][ni][1] * scale + b1v;
                acc_s[mi][ni][2] = acc_s[mi][ni][2] * scale + b0v;
                acc_s[mi][ni][3] = acc_s[mi][ni][3] * scale + b1v;
            }

        #pragma unroll
        for (int mi = 0; mi < 2; mi++) {
            #pragma unroll
            for (int hf = 0; hf < 2; hf++) {
                int c0 = hf * 2, c1 = hf * 2 + 1;
                float mx = -1e30f;
                #pragma unroll
                for (int ni = 0; ni < 8; ni++)
                    mx = fmaxf(mx, fmaxf(acc_s[mi][ni][c0], acc_s[mi][ni][c1]));
                mx = fmaxf(mx, __shfl_xor_sync(0xffffffffu, mx, 1));
                mx = fmaxf(mx, __shfl_xor_sync(0xffffffffu, mx, 2));
                int si = mi * 2 + hf;
                float mn = fmaxf(m_run[si], mx);
                float corr = __expf(m_run[si] - mn);
                m_run[si] = mn;
                float rs = 0.0f;
                #pragma unroll
                for (int ni = 0; ni < 8; ni++) {
                    float p0 = __expf(acc_s[mi][ni][c0] - mn);
                    float p1 = __expf(acc_s[mi][ni][c1] - mn);
                    acc_s[mi][ni][c0] = p0;
                    acc_s[mi][ni][c1] = p1;
                    rs += p0 + p1;
                }
                rs += __shfl_xor_sync(0xffffffffu, rs, 1);
                rs += __shfl_xor_sync(0xffffffffu, rs, 2);
                l_run[si] = l_run[si] * corr + rs;
                #pragma unroll
                for (int ni = 0; ni < 8; ni++) {
                    acc_o[mi][ni][c0] *= corr;
                    acc_o[mi][ni][c1] *= corr;
                }
            }
        }

        #pragma unroll
        for (int t = 0; t < 4; t++) {
            uint32_t aph[2][4], apl[2][4];
            #pragma unroll
            for (int mi = 0; mi < 2; mi++) {
                float* S0 = acc_s[mi][2 * t];
                float* S1 = acc_s[mi][2 * t + 1];
                __half h0, l0, h1, l1;
                split2h(S0[0], h0, l0); split2h(S0[1], h1, l1);
                aph[mi][0] = pack_h2(h0, h1); apl[mi][0] = pack_h2(l0, l1);
                split2h(S0[2], h0, l0); split2h(S0[3], h1, l1);
                aph[mi][1] = pack_h2(h0, h1); apl[mi][1] = pack_h2(l0, l1);
                split2h(S1[0], h0, l0); split2h(S1[1], h1, l1);
                aph[mi][2] = pack_h2(h0, h1); apl[mi][2] = pack_h2(l0, l1);
                split2h(S1[2], h0, l0); split2h(S1[3], h1, l1);
                aph[mi][3] = pack_h2(h0, h1); apl[mi][3] = pack_h2(l0, l1);
            }
            #pragma unroll
            for (int g = 0; g < 4; g++) {
                uint32_t vr = g * 16 + ldrow;
                uint32_t w4[4];
                ldm_x4(w4, sb + SM_VT + vr * AVP + chunk * 128 + t * 32 + ldoff);
                uint32_t b0[2] = {w4[0], w4[2]}, b1[2] = {w4[1], w4[3]};
                #pragma unroll
                for (int mi = 0; mi < 2; mi++) {
                    mma16816(acc_o[mi][2 * g],     aph[mi], b0);
                    mma16816(acc_o[mi][2 * g + 1], aph[mi], b1);
                    mma16816(acc_o[mi][2 * g],     apl[mi], b0);
                    mma16816(acc_o[mi][2 * g + 1], apl[mi], b1);
                }
            }
        }
    }

    const size_t obase = ((size_t)b * S_) * H_ + (size_t)h * HD_;
    #pragma unroll
    for (int mi = 0; mi < 2; mi++) {
        float inv0 = 1.0f / l_run[mi * 2];
        float inv1 = 1.0f / l_run[mi * 2 + 1];
        int r0 = w * 32 + mi * 16 + tr;
        int r1 = r0 + 8;
        #pragma unroll
        for (int ni = 0; ni < 8; ni++) {
            int d = ni * 8 + tqc;
            float v0 = acc_o[mi][ni][0] * inv0, v1 = acc_o[mi][ni][1] * inv0;
            float v2 = acc_o[mi][ni][2] * inv1, v3 = acc_o[mi][ni][3] * inv1;
            *(uint32_t*)(Oh + obase + (size_t)r0 * H_ + d) =
                pack_h2(__float2half_rn(v0), __float2half_rn(v1));
            *(uint32_t*)(Oh + obase + (size_t)r1 * H_ + d) =
                pack_h2(__float2half_rn(v2), __float2half_rn(v3));
        }
    }
}

// ---------------- Classification head ----------------
__global__ void head_kernel(const float* __restrict__ h,
                            const int* __restrict__ ann,
                            const float* __restrict__ hw,
                            const float* __restrict__ hb,
                            float* __restrict__ out) {
    __shared__ float red[32];
    int b = blockIdx.x;
    int tid = threadIdx.x;
    int a = ann[b];
    const float* cls = h + (size_t)b * S_ * H_;
    const float* w = hw + (size_t)a * H_ * NL_;
    float a0 = 0.0f, a1 = 0.0f;
    for (int i = tid; i < H_; i += 256) {
        float c = cls[i];
        a0 = fmaf(c, w[i * NL_ + 0], a0);
        a1 = fmaf(c, w[i * NL_ + 1], a1);
    }
    a0 = block_sum(a0, red);
    a1 = block_sum(a1, red);
    if (tid == 0) {
        out[b * NL_ + 0] = a0 + hb[a * NL_ + 0];
        out[b * NL_ + 1] = a1 + hb[a * NL_ + 1];
    }
}

// ---------------- Host launcher ----------------
extern "C" void kernel_launch(void* const* d_in, const int* in_sizes, int n_in,
                              void* d_out, int out_size) {
    (void)in_sizes; (void)n_in; (void)out_size;
    const int*   ids   = (const int*)  d_in[0];
    const int*   amask = (const int*)  d_in[1];
    const int*   tt    = (const int*)  d_in[2];
    const int*   ann   = (const int*)  d_in[3];
    const float* we    = (const float*)d_in[4];
    const float* pe    = (const float*)d_in[5];
    const float* te    = (const float*)d_in[6];
    const float* elns  = (const float*)d_in[7];
    const float* elnb  = (const float*)d_in[8];
    const float* Wq    = (const float*)d_in[9];
    const float* bq    = (const float*)d_in[10];
    const float* Wk    = (const float*)d_in[11];
    const float* bk    = (const float*)d_in[12];
    const float* Wv    = (const float*)d_in[13];
    const float* bv    = (const float*)d_in[14];
    const float* Wo    = (const float*)d_in[15];
    const float* bo    = (const float*)d_in[16];
    const float* l1s   = (const float*)d_in[17];
    const float* l1b   = (const float*)d_in[18];
    const float* W1    = (const float*)d_in[19];
    const float* b1    = (const float*)d_in[20];
    const float* W2    = (const float*)d_in[21];
    const float* b2    = (const float*)d_in[22];
    const float* l2s   = (const float*)d_in[23];
    const float* l2b   = (const float*)d_in[24];
    const float* hw    = (const float*)d_in[25];
    const float* hb    = (const float*)d_in[26];
    float* out = (float*)d_out;

    float *h, *tmp, *qkv, *bqkv;
    __half *hh, *ch, *fh;
    __half *wqkv, *wo, *w1, *w2;
    cudaGetSymbolAddress((void**)&h,    g_h);
    cudaGetSymbolAddress((void**)&tmp,  g_tmp);
    cudaGetSymbolAddress((void**)&qkv,  g_qkv);
    cudaGetSymbolAddress((void**)&bqkv, g_bqkv);
    cudaGetSymbolAddress((void**)&hh,   g_hh);
    cudaGetSymbolAddress((void**)&ch,   g_ch);
    cudaGetSymbolAddress((void**)&fh,   g_fh);
    cudaGetSymbolAddress((void**)&wqkv, g_Wqkv);
    cudaGetSymbolAddress((void**)&wo,   g_Wo);
    cudaGetSymbolAddress((void**)&w1,   g_W1);
    cudaGetSymbolAddress((void**)&w2,   g_W2);

    cudaFuncSetAttribute(attn_mma,
                         cudaFuncAttributeMaxDynamicSharedMemorySize, ASMEM);
    cudaFuncSetAttribute(gemm_mma,
                         cudaFuncAttributeMaxDynamicSharedMemorySize, GSMEM);

    dim3 pb(32, 8);
    // Keep QKV gemm at my-launch #4 (process launch #6 under ncu -s 5).
    concat_bias_kernel<<<(L_ * QS_ + 255) / 256, 256>>>(bq, bk, bv, bqkv);
    prep_w4_kernel<<<dim3(H_ / 32, H_ / 32, L_ * 4), pb>>>(Wq, Wk, Wv, Wo, wqkv, wo);
    embed_ln_kernel<<<NTOK, 256>>>(ids, tt, we, pe, te, elns, elnb, h, hh);

    dim3 gQKV(QS_ / 128, NTOK / 128);  // (18, 128)
    dim3 gH  (H_  / 128, NTOK / 128);  // (6, 128)
    dim3 gFF (FF_ / 128, NTOK / 128);  // (24, 128)

    for (int l = 0; l < L_; l++) {
        size_t wqo = (size_t)l * QS_ * H_;
        size_t woo = (size_t)l * H_ * H_;
        size_t wfo = (size_t)l * H_ * FF_;

        gemm_mma<<<gQKV, 256, GSMEM>>>(hh, wqkv + wqo,
                                       bqkv + (size_t)l * QS_,
                                       qkv, nullptr, NTOK, QS_, H_, 0);

        if (l == 0) {
            prep_w_kernel<<<dim3(FF_ / 32, H_ / 32, L_), pb>>>(W1, w1, H_, FF_);
            prep_w_kernel<<<dim3(H_ / 32, FF_ / 32, L_), pb>>>(W2, w2, FF_, H_);
        }

        attn_mma<<<B_ * NH_, 256, ASMEM>>>(qkv, amask, ch);

        gemm_mma<<<gH, 256, GSMEM>>>(ch, wo + woo,
                                     bo + (size_t)l * H_,
                                     tmp, nullptr, NTOK, H_, H_, 0);
        add_ln_kernel<<<NTOK, 256>>>(h, tmp, l1s + (size_t)l * H_, l1b + (size_t)l * H_, hh);

        gemm_mma<<<gFF, 256, GSMEM>>>(hh, w1 + wfo,
                                      b1 + (size_t)l * FF_,
                                      nullptr, fh, NTOK, FF_, H_, 1);
        gemm_mma<<<gH, 256, GSMEM>>>(fh, w2 + wfo,
                                     b2 + (size_t)l * H_,
                                     tmp, nullptr, NTOK, H_, FF_, 0);
        add_ln_kernel<<<NTOK, 256>>>(h, tmp, l2s + (size_t)l * H_, l2b + (size_t)l * H_, hh);
    }

    head_kernel<<<B_, 256>>>(h, ann, hw, hb, out);
}